// round 3
// baseline (speedup 1.0000x reference)
#include <cuda_runtime.h>

#define SEQ   2048
#define EMB   1024
#define NH    16
#define HD    64
#define BATCH 2
#define MTOT  (BATCH*SEQ)     // 4096
#define BHTOT (BATCH*NH)      // 32

// Scratch (no allocations allowed): Q/K/V in [B*H, N, D], H-concat in [B*N, E]
__device__ float g_Q[BHTOT*SEQ*HD];
__device__ float g_K[BHTOT*SEQ*HD];
__device__ float g_V[BHTOT*SEQ*HD];
__device__ float g_Hc[MTOT*EMB];

// ---------------------------------------------------------------------------
// SGEMM core: C[M=4096, N=1024] = A[M,1024] @ W^T + bias
// BM=128, BN=128, BK=8, 256 threads, 8x8 microtile.
// ---------------------------------------------------------------------------

__global__ __launch_bounds__(256) void qkv_gemm(
    const float* __restrict__ x,
    const float* __restrict__ Wq, const float* __restrict__ bq,
    const float* __restrict__ Wk, const float* __restrict__ bk,
    const float* __restrict__ Wv, const float* __restrict__ bv)
{
    const float* W; const float* bias; float* out;
    if (blockIdx.z == 0)      { W = Wq; bias = bq; out = g_Q; }
    else if (blockIdx.z == 1) { W = Wk; bias = bk; out = g_K; }
    else                      { W = Wv; bias = bv; out = g_V; }

    __shared__ float As[8][128];
    __shared__ float Bs[8][128];

    const int tid = threadIdx.x;
    const int tx = tid & 15, ty = tid >> 4;
    const int bm = blockIdx.x * 128;
    const int bn = blockIdx.y * 128;
    const int lrow = tid >> 1;
    const int lk4  = (tid & 1) * 4;

    float acc[8][8];
#pragma unroll
    for (int i = 0; i < 8; i++)
#pragma unroll
        for (int j = 0; j < 8; j++) acc[i][j] = 0.f;

    const float* aptr = x + (size_t)(bm + lrow) * EMB + lk4;
    const float* bptr = W + (size_t)(bn + lrow) * EMB + lk4;

    for (int k0 = 0; k0 < EMB; k0 += 8) {
        float4 av  = *(const float4*)(aptr + k0);
        float4 bv4 = *(const float4*)(bptr + k0);
        __syncthreads();
        As[lk4+0][lrow] = av.x;  As[lk4+1][lrow] = av.y;
        As[lk4+2][lrow] = av.z;  As[lk4+3][lrow] = av.w;
        Bs[lk4+0][lrow] = bv4.x; Bs[lk4+1][lrow] = bv4.y;
        Bs[lk4+2][lrow] = bv4.z; Bs[lk4+3][lrow] = bv4.w;
        __syncthreads();
#pragma unroll
        for (int kk = 0; kk < 8; kk++) {
            float a[8], b[8];
            *(float4*)&a[0] = *(const float4*)&As[kk][ty*8];
            *(float4*)&a[4] = *(const float4*)&As[kk][ty*8+4];
            *(float4*)&b[0] = *(const float4*)&Bs[kk][tx*8];
            *(float4*)&b[4] = *(const float4*)&Bs[kk][tx*8+4];
#pragma unroll
            for (int i = 0; i < 8; i++)
#pragma unroll
                for (int j = 0; j < 8; j++)
                    acc[i][j] += a[i] * b[j];
        }
    }

    // Epilogue: scatter into [b*NH+h][n][d] layout for attention.
    const int c0 = bn + tx*8;     // output channel base (8 cols, never crosses a head)
    const int h  = c0 >> 6;
    const int d0 = c0 & 63;
    float bb[8];
#pragma unroll
    for (int j = 0; j < 8; j++) bb[j] = bias[c0 + j];
#pragma unroll
    for (int i = 0; i < 8; i++) {
        const int m = bm + ty*8 + i;
        const int b = m >> 11;          // /SEQ
        const int n = m & (SEQ-1);
        float* op = out + ((size_t)(b*NH + h)*SEQ + n)*HD + d0;
        float4 v0 = make_float4(acc[i][0]+bb[0], acc[i][1]+bb[1],
                                acc[i][2]+bb[2], acc[i][3]+bb[3]);
        float4 v1 = make_float4(acc[i][4]+bb[4], acc[i][5]+bb[5],
                                acc[i][6]+bb[6], acc[i][7]+bb[7]);
        *(float4*)(op)   = v0;
        *(float4*)(op+4) = v1;
    }
}

__global__ __launch_bounds__(256) void out_gemm(
    const float* __restrict__ Wo, const float* __restrict__ bo,
    float* __restrict__ outp)
{
    __shared__ float As[8][128];
    __shared__ float Bs[8][128];

    const int tid = threadIdx.x;
    const int tx = tid & 15, ty = tid >> 4;
    const int bm = blockIdx.x * 128;
    const int bn = blockIdx.y * 128;
    const int lrow = tid >> 1;
    const int lk4  = (tid & 1) * 4;

    float acc[8][8];
#pragma unroll
    for (int i = 0; i < 8; i++)
#pragma unroll
        for (int j = 0; j < 8; j++) acc[i][j] = 0.f;

    const float* aptr = g_Hc + (size_t)(bm + lrow) * EMB + lk4;
    const float* bptr = Wo   + (size_t)(bn + lrow) * EMB + lk4;

    for (int k0 = 0; k0 < EMB; k0 += 8) {
        float4 av  = *(const float4*)(aptr + k0);
        float4 bv4 = *(const float4*)(bptr + k0);
        __syncthreads();
        As[lk4+0][lrow] = av.x;  As[lk4+1][lrow] = av.y;
        As[lk4+2][lrow] = av.z;  As[lk4+3][lrow] = av.w;
        Bs[lk4+0][lrow] = bv4.x; Bs[lk4+1][lrow] = bv4.y;
        Bs[lk4+2][lrow] = bv4.z; Bs[lk4+3][lrow] = bv4.w;
        __syncthreads();
#pragma unroll
        for (int kk = 0; kk < 8; kk++) {
            float a[8], b[8];
            *(float4*)&a[0] = *(const float4*)&As[kk][ty*8];
            *(float4*)&a[4] = *(const float4*)&As[kk][ty*8+4];
            *(float4*)&b[0] = *(const float4*)&Bs[kk][tx*8];
            *(float4*)&b[4] = *(const float4*)&Bs[kk][tx*8+4];
#pragma unroll
            for (int i = 0; i < 8; i++)
#pragma unroll
                for (int j = 0; j < 8; j++)
                    acc[i][j] += a[i] * b[j];
        }
    }

    float bb[8];
#pragma unroll
    for (int j = 0; j < 8; j++) bb[j] = bo[bn + tx*8 + j];
#pragma unroll
    for (int i = 0; i < 8; i++) {
        float* op = outp + (size_t)(bm + ty*8 + i)*EMB + bn + tx*8;
        float4 v0 = make_float4(acc[i][0]+bb[0], acc[i][1]+bb[1],
                                acc[i][2]+bb[2], acc[i][3]+bb[3]);
        float4 v1 = make_float4(acc[i][4]+bb[4], acc[i][5]+bb[5],
                                acc[i][6]+bb[6], acc[i][7]+bb[7]);
        *(float4*)(op)   = v0;
        *(float4*)(op+4) = v1;
    }
}

// ---------------------------------------------------------------------------
// Flash attention: BM=128 queries, BN=64 keys per tile, D=64. 256 threads.
// Thread (ty,tx): ty=tid/16 -> rows r0=ty*8..+7 ; tx=tid%16 -> cols c0=tx*4..+3
// Smem (dynamic, 96 KB): Qs[d][128] (x8 scale folded), Ks[d][64], Vs[c][64],
// Ps[c][128]. Transposed d-major layouts make all compute loads LDS.128 with
// broadcast/conflict-free access; global loads for Q/K pay a strided pattern
// once per tile (L2-resident, cheap).
// ---------------------------------------------------------------------------

#define ATT_SMEM_FLOATS (64*128 + 64*64 + 64*64 + 64*128)  // 24576 floats = 96 KB

__global__ __launch_bounds__(256) void attn_kernel()
{
    extern __shared__ float sm[];
    float* Qs = sm;                  // [64][128]
    float* Ks = Qs + 64*128;         // [64][64]
    float* Vs = Ks + 64*64;          // [64][64]
    float* Ps = Vs + 64*64;          // [64][128]

    const int tid = threadIdx.x;
    const int tx = tid & 15, ty = tid >> 4;
    const int r0 = ty * 8;
    const int c0 = tx * 4;

    const int bh   = blockIdx.y;
    const int qblk = blockIdx.x;
    const float* Qg = g_Q + ((size_t)bh*SEQ + qblk*128)*HD;
    const float* Kg = g_K + (size_t)bh*SEQ*HD;
    const float* Vg = g_V + (size_t)bh*SEQ*HD;

    // Load Q tile transposed [d][r], fold the x8 logit scale (sqrt(HD)).
#pragma unroll
    for (int i = 0; i < 8; i++) {
        int s  = tid + i*256;
        int r  = s & 127;
        int d4 = (s >> 7) * 4;
        float4 v = *(const float4*)(Qg + r*HD + d4);
        Qs[(d4+0)*128 + r] = v.x * 8.0f;
        Qs[(d4+1)*128 + r] = v.y * 8.0f;
        Qs[(d4+2)*128 + r] = v.z * 8.0f;
        Qs[(d4+3)*128 + r] = v.w * 8.0f;
    }

    float m_i[8], l_i[8], o[8][4];
#pragma unroll
    for (int i = 0; i < 8; i++) {
        m_i[i] = -1e30f; l_i[i] = 0.f;
#pragma unroll
        for (int j = 0; j < 4; j++) o[i][j] = 0.f;
    }

    for (int kt = 0; kt < SEQ; kt += 64) {
        __syncthreads();   // prior tile's P@V done with Ps/Vs; Q ready on iter 0
        // K tile transposed [d][c]
#pragma unroll
        for (int i = 0; i < 4; i++) {
            int s  = tid + i*256;
            int c  = s & 63;
            int d4 = (s >> 6) * 4;
            float4 v = *(const float4*)(Kg + (size_t)(kt + c)*HD + d4);
            Ks[(d4+0)*64 + c] = v.x;
            Ks[(d4+1)*64 + c] = v.y;
            Ks[(d4+2)*64 + c] = v.z;
            Ks[(d4+3)*64 + c] = v.w;
        }
        // V tile straight [c][d]
#pragma unroll
        for (int i = 0; i < 4; i++) {
            int s  = tid + i*256;
            int c  = s >> 4;
            int d4 = (s & 15) * 4;
            *(float4*)(Vs + c*HD + d4) = *(const float4*)(Vg + (size_t)(kt + c)*HD + d4);
        }
        __syncthreads();

        // S[8][4] = (8*Q) K^T
        float sreg[8][4];
#pragma unroll
        for (int i = 0; i < 8; i++)
#pragma unroll
            for (int j = 0; j < 4; j++) sreg[i][j] = 0.f;

#pragma unroll 8
        for (int d = 0; d < 64; d++) {
            float a[8], b[4];
            *(float4*)&a[0] = *(const float4*)&Qs[d*128 + r0];
            *(float4*)&a[4] = *(const float4*)&Qs[d*128 + r0 + 4];
            *(float4*)&b[0] = *(const float4*)&Ks[d*64 + c0];
#pragma unroll
            for (int i = 0; i < 8; i++)
#pragma unroll
                for (int j = 0; j < 4; j++)
                    sreg[i][j] += a[i] * b[j];
        }

        // Online softmax. Each row lives in the 16 contiguous tx lanes.
#pragma unroll
        for (int i = 0; i < 8; i++) {
            float mx = fmaxf(fmaxf(sreg[i][0], sreg[i][1]),
                             fmaxf(sreg[i][2], sreg[i][3]));
#pragma unroll
            for (int off = 1; off < 16; off <<= 1)
                mx = fmaxf(mx, __shfl_xor_sync(0xffffffffu, mx, off));
            float nm = fmaxf(m_i[i], mx);
            float al = __expf(m_i[i] - nm);
            m_i[i] = nm;
            float rs = 0.f;
#pragma unroll
            for (int j = 0; j < 4; j++) {
                sreg[i][j] = __expf(sreg[i][j] - nm);
                rs += sreg[i][j];
            }
#pragma unroll
            for (int off = 1; off < 16; off <<= 1)
                rs += __shfl_xor_sync(0xffffffffu, rs, off);
            l_i[i] = l_i[i]*al + rs;
#pragma unroll
            for (int j = 0; j < 4; j++) o[i][j] *= al;
        }

        // Stage P transposed [c][r] for the P@V matmul.
#pragma unroll
        for (int j = 0; j < 4; j++) {
            *(float4*)&Ps[(c0+j)*128 + r0] =
                make_float4(sreg[0][j], sreg[1][j], sreg[2][j], sreg[3][j]);
            *(float4*)&Ps[(c0+j)*128 + r0 + 4] =
                make_float4(sreg[4][j], sreg[5][j], sreg[6][j], sreg[7][j]);
        }
        __syncthreads();

        // O[8][4] += P @ V   (thread's d-columns are c0..c0+3)
#pragma unroll 8
        for (int c = 0; c < 64; c++) {
            float p[8], vv[4];
            *(float4*)&p[0]  = *(const float4*)&Ps[c*128 + r0];
            *(float4*)&p[4]  = *(const float4*)&Ps[c*128 + r0 + 4];
            *(float4*)&vv[0] = *(const float4*)&Vs[c*HD + c0];
#pragma unroll
            for (int i = 0; i < 8; i++)
#pragma unroll
                for (int j = 0; j < 4; j++)
                    o[i][j] += p[i] * vv[j];
        }
    }

    // Normalize and write to concat layout [b][tok][h*64+d]
    const int b = bh >> 4;
    const int h = bh & 15;
#pragma unroll
    for (int i = 0; i < 8; i++) {
        float inv = 1.0f / l_i[i];
        int tok = qblk*128 + r0 + i;
        float* op = g_Hc + ((size_t)(b*SEQ + tok))*EMB + h*HD + c0;
        *(float4*)op = make_float4(o[i][0]*inv, o[i][1]*inv,
                                   o[i][2]*inv, o[i][3]*inv);
    }
}

// ---------------------------------------------------------------------------

extern "C" void kernel_launch(void* const* d_in, const int* in_sizes, int n_in,
                              void* d_out, int out_size)
{
    (void)in_sizes; (void)n_in; (void)out_size;
    const float* x  = (const float*)d_in[0];
    const float* Wq = (const float*)d_in[1];
    const float* bq = (const float*)d_in[2];
    const float* Wk = (const float*)d_in[3];
    const float* bk = (const float*)d_in[4];
    const float* Wv = (const float*)d_in[5];
    const float* bv = (const float*)d_in[6];
    const float* Wo = (const float*)d_in[7];
    const float* bo = (const float*)d_in[8];
    float* out = (float*)d_out;

    cudaFuncSetAttribute(attn_kernel,
                         cudaFuncAttributeMaxDynamicSharedMemorySize,
                         ATT_SMEM_FLOATS * (int)sizeof(float));

    qkv_gemm<<<dim3(32, 8, 3), 256>>>(x, Wq, bq, Wk, bk, Wv, bv);
    attn_kernel<<<dim3(SEQ/128, BHTOT), 256, ATT_SMEM_FLOATS * sizeof(float)>>>();
    out_gemm<<<dim3(32, 8), 256>>>(Wo, bo, out);
}

// round 6
// speedup vs baseline: 1.3921x; 1.3921x over previous
#include <cuda_runtime.h>
#include <cuda_bf16.h>
#include <cstdint>

#define SEQ   2048
#define EMB   1024
#define NH    16
#define HD    64
#define BATCH 2
#define MTOT  (BATCH*SEQ)     // 4096
#define BHTOT (BATCH*NH)      // 32

// ---------------- scratch (static device globals; no allocations) ----------
__device__ float g_Q[BHTOT*SEQ*HD];
__device__ float g_K[BHTOT*SEQ*HD];
__device__ float g_V[BHTOT*SEQ*HD];

__device__ __nv_bfloat16 g_Xhi[MTOT*EMB],  g_Xlo[MTOT*EMB];
__device__ __nv_bfloat16 g_Wqhi[EMB*EMB],  g_Wqlo[EMB*EMB];
__device__ __nv_bfloat16 g_Wkhi[EMB*EMB],  g_Wklo[EMB*EMB];
__device__ __nv_bfloat16 g_Wvhi[EMB*EMB],  g_Wvlo[EMB*EMB];
__device__ __nv_bfloat16 g_Wohi[EMB*EMB],  g_Wolo[EMB*EMB];
__device__ __nv_bfloat16 g_Hchi[MTOT*EMB], g_Hclo[MTOT*EMB];

// ---------------- PTX helpers (all pre-Blackwell features: safe on sm_103) --
__device__ __forceinline__ uint32_t smem_u32(const void* p) {
    uint32_t a;
    asm("{ .reg .u64 t; cvta.to.shared.u64 t, %1; cvt.u32.u64 %0, t; }"
        : "=r"(a) : "l"(p));
    return a;
}
__device__ __forceinline__ void cp16(uint32_t sdst, const void* gsrc) {
    asm volatile("cp.async.cg.shared.global [%0], [%1], 16;"
                 :: "r"(sdst), "l"(gsrc));
}
__device__ __forceinline__ void ldsm_x4(uint32_t a[4], uint32_t addr) {
    asm volatile("ldmatrix.sync.aligned.m8n8.x4.shared.b16 {%0,%1,%2,%3}, [%4];"
                 : "=r"(a[0]), "=r"(a[1]), "=r"(a[2]), "=r"(a[3]) : "r"(addr));
}
__device__ __forceinline__ void ldsm_x2(uint32_t a[2], uint32_t addr) {
    asm volatile("ldmatrix.sync.aligned.m8n8.x2.shared.b16 {%0,%1}, [%2];"
                 : "=r"(a[0]), "=r"(a[1]) : "r"(addr));
}
__device__ __forceinline__ void mma16816(float d[4], const uint32_t a[4],
                                         const uint32_t b[2]) {
    asm volatile(
        "mma.sync.aligned.m16n8k16.row.col.f32.bf16.bf16.f32 "
        "{%0,%1,%2,%3}, {%4,%5,%6,%7}, {%8,%9}, {%0,%1,%2,%3};"
        : "+f"(d[0]), "+f"(d[1]), "+f"(d[2]), "+f"(d[3])
        : "r"(a[0]), "r"(a[1]), "r"(a[2]), "r"(a[3]), "r"(b[0]), "r"(b[1]));
}

// ---------------- mma.sync GEMM config -------------------------------------
// C[4096,1024] = A[4096,1024] @ W^T, bf16 hi/lo 3-pass, fp32 accum in regs.
// Block 128x128, warps 2x4 (warp tile 64x32), K-chunk 32, 2-stage cp.async.
#define BK 32
#define NCHUNK (EMB/BK)       // 32
#define STRB 80               // smem row stride bytes (32 bf16 + 8 pad)
#define OFF_AHI 0
#define OFF_ALO 10240
#define OFF_BHI 20480
#define OFF_BLO 30720
#define STAGE_BYTES 40960
#define GEMM_SMEM_BYTES (2*STAGE_BYTES)   // 80 KB

__device__ __forceinline__ void gemm_load_chunk(
    uint32_t sb, int stage, int kc, int bm, int bn,
    const __nv_bfloat16* __restrict__ Ahi, const __nv_bfloat16* __restrict__ Alo,
    const __nv_bfloat16* __restrict__ Bhi, const __nv_bfloat16* __restrict__ Blo,
    int tid)
{
    const uint32_t st = sb + stage * STAGE_BYTES;
#pragma unroll
    for (int i = 0; i < 2; i++) {
        int idx = tid + i * 256;          // 512 16B-chunks per matrix
        int row = idx >> 2, ch = idx & 3;
        uint32_t so = (uint32_t)(row * STRB + ch * 16);
        size_t ga = (size_t)(bm + row) * EMB + kc * BK + ch * 8;
        size_t gb = (size_t)(bn + row) * EMB + kc * BK + ch * 8;
        cp16(st + OFF_AHI + so, Ahi + ga);
        cp16(st + OFF_ALO + so, Alo + ga);
        cp16(st + OFF_BHI + so, Bhi + gb);
        cp16(st + OFF_BLO + so, Blo + gb);
    }
    asm volatile("cp.async.commit_group;" ::: "memory");
}

__device__ __forceinline__ void gemm_compute_stage(
    uint32_t sbase, int wm, int wn, int lane, float acc[4][4][4])
{
    const int ra      = lane & 15;
    const uint32_t ka = (uint32_t)((lane >> 4) * 16);
    const int nb      = lane & 7;
    const uint32_t kb = (uint32_t)(((lane >> 3) & 1) * 16);
#pragma unroll
    for (int ks = 0; ks < 2; ks++) {
        uint32_t ah[4][4], al[4][4], bh[4][2], bl[4][2];
#pragma unroll
        for (int mi = 0; mi < 4; mi++) {
            uint32_t r = sbase + (uint32_t)((wm*64 + mi*16 + ra) * STRB) + ks*32 + ka;
            ldsm_x4(ah[mi], r + OFF_AHI);
            ldsm_x4(al[mi], r + OFF_ALO);
        }
#pragma unroll
        for (int ni = 0; ni < 4; ni++) {
            uint32_t r = sbase + (uint32_t)((wn*32 + ni*8 + nb) * STRB) + ks*32 + kb;
            ldsm_x2(bh[ni], r + OFF_BHI);
            ldsm_x2(bl[ni], r + OFF_BLO);
        }
#pragma unroll
        for (int mi = 0; mi < 4; mi++)
#pragma unroll
            for (int ni = 0; ni < 4; ni++) {
                mma16816(acc[mi][ni], ah[mi], bh[ni]);
                mma16816(acc[mi][ni], ah[mi], bl[ni]);
                mma16816(acc[mi][ni], al[mi], bh[ni]);
            }
    }
}

__device__ __forceinline__ void gemm_mainloop(
    uint32_t sb, int bm, int bn,
    const __nv_bfloat16* Ahi, const __nv_bfloat16* Alo,
    const __nv_bfloat16* Bhi, const __nv_bfloat16* Blo,
    int tid, int wm, int wn, int lane, float acc[4][4][4])
{
#pragma unroll
    for (int mi = 0; mi < 4; mi++)
#pragma unroll
        for (int ni = 0; ni < 4; ni++)
#pragma unroll
            for (int q = 0; q < 4; q++) acc[mi][ni][q] = 0.f;

    gemm_load_chunk(sb, 0, 0, bm, bn, Ahi, Alo, Bhi, Blo, tid);

    for (int c = 0; c < NCHUNK; c++) {
        if (c + 1 < NCHUNK) {
            gemm_load_chunk(sb, (c + 1) & 1, c + 1, bm, bn, Ahi, Alo, Bhi, Blo, tid);
            asm volatile("cp.async.wait_group 1;" ::: "memory");
        } else {
            asm volatile("cp.async.wait_group 0;" ::: "memory");
        }
        __syncthreads();
        gemm_compute_stage(sb + (uint32_t)((c & 1) * STAGE_BYTES), wm, wn, lane, acc);
        __syncthreads();
    }
}

// ---------------- split kernel: fp32 -> (bf16 hi, bf16 lo) -----------------
__global__ __launch_bounds__(256) void split_kernel(
    const float* __restrict__ x,
    const float* __restrict__ Wq, const float* __restrict__ Wk,
    const float* __restrict__ Wv, const float* __restrict__ Wo)
{
    const float* src; __nv_bfloat16* hi; __nv_bfloat16* lo; int n4;
    switch (blockIdx.z) {
        case 0:  src = x;  hi = g_Xhi;  lo = g_Xlo;  n4 = MTOT*EMB/4; break;
        case 1:  src = Wq; hi = g_Wqhi; lo = g_Wqlo; n4 = EMB*EMB/4;  break;
        case 2:  src = Wk; hi = g_Wkhi; lo = g_Wklo; n4 = EMB*EMB/4;  break;
        case 3:  src = Wv; hi = g_Wvhi; lo = g_Wvlo; n4 = EMB*EMB/4;  break;
        default: src = Wo; hi = g_Wohi; lo = g_Wolo; n4 = EMB*EMB/4;  break;
    }
    for (int i = blockIdx.x * blockDim.x + threadIdx.x; i < n4;
         i += gridDim.x * blockDim.x) {
        float4 v = ((const float4*)src)[i];
        __nv_bfloat16 h0 = __float2bfloat16(v.x);
        __nv_bfloat16 h1 = __float2bfloat16(v.y);
        __nv_bfloat16 h2 = __float2bfloat16(v.z);
        __nv_bfloat16 h3 = __float2bfloat16(v.w);
        __nv_bfloat16 l0 = __float2bfloat16(v.x - __bfloat162float(h0));
        __nv_bfloat16 l1 = __float2bfloat16(v.y - __bfloat162float(h1));
        __nv_bfloat16 l2 = __float2bfloat16(v.z - __bfloat162float(h2));
        __nv_bfloat16 l3 = __float2bfloat16(v.w - __bfloat162float(h3));
        ((__nv_bfloat162*)hi)[2*i]   = __halves2bfloat162(h0, h1);
        ((__nv_bfloat162*)hi)[2*i+1] = __halves2bfloat162(h2, h3);
        ((__nv_bfloat162*)lo)[2*i]   = __halves2bfloat162(l0, l1);
        ((__nv_bfloat162*)lo)[2*i+1] = __halves2bfloat162(l2, l3);
    }
}

// ---------------- QKV projection (mma.sync tensor path) ---------------------
__global__ __launch_bounds__(256) void qkv_gemm_tc(
    const float* __restrict__ bq, const float* __restrict__ bk,
    const float* __restrict__ bv)
{
    extern __shared__ char dsm[];
    uint32_t sb = smem_u32(dsm);
    const int tid = threadIdx.x, wid = tid >> 5, lane = tid & 31;
    const int wm = wid >> 2, wn = wid & 3;
    const int bm = blockIdx.x * 128, bn = blockIdx.y * 128;

    const __nv_bfloat16 *Bhi, *Blo; const float* bias; float* outp;
    if (blockIdx.z == 0)      { Bhi = g_Wqhi; Blo = g_Wqlo; bias = bq; outp = g_Q; }
    else if (blockIdx.z == 1) { Bhi = g_Wkhi; Blo = g_Wklo; bias = bk; outp = g_K; }
    else                      { Bhi = g_Wvhi; Blo = g_Wvlo; bias = bv; outp = g_V; }

    float acc[4][4][4];
    gemm_mainloop(sb, bm, bn, g_Xhi, g_Xlo, Bhi, Blo, tid, wm, wn, lane, acc);

    // Epilogue: scatter into [b*NH+h][n][d] with bias.
    const int g  = lane >> 2, tg = lane & 3;
#pragma unroll
    for (int ni = 0; ni < 4; ni++) {
        const int c0 = bn + wn*32 + ni*8 + 2*tg;
        const float bx = bias[c0], by = bias[c0 + 1];
        const int h  = c0 >> 6;
        const int d0 = c0 & 63;
#pragma unroll
        for (int mi = 0; mi < 4; mi++) {
#pragma unroll
            for (int half = 0; half < 2; half++) {
                const int r = bm + wm*64 + mi*16 + g + half*8;
                const int b = r >> 11;
                const int n = r & (SEQ - 1);
                float* op = outp + ((size_t)((b << 4) + h) * SEQ + n) * HD + d0;
                float2 v = make_float2(acc[mi][ni][half*2 + 0] + bx,
                                       acc[mi][ni][half*2 + 1] + by);
                *(float2*)op = v;
            }
        }
    }
}

// ---------------- output projection (mma.sync tensor path) ------------------
__global__ __launch_bounds__(256) void out_gemm_tc(
    const float* __restrict__ bo, float* __restrict__ outp)
{
    extern __shared__ char dsm[];
    uint32_t sb = smem_u32(dsm);
    const int tid = threadIdx.x, wid = tid >> 5, lane = tid & 31;
    const int wm = wid >> 2, wn = wid & 3;
    const int bm = blockIdx.x * 128, bn = blockIdx.y * 128;

    float acc[4][4][4];
    gemm_mainloop(sb, bm, bn, g_Hchi, g_Hclo, g_Wohi, g_Wolo,
                  tid, wm, wn, lane, acc);

    const int g  = lane >> 2, tg = lane & 3;
#pragma unroll
    for (int ni = 0; ni < 4; ni++) {
        const int c0 = bn + wn*32 + ni*8 + 2*tg;
        const float bx = bo[c0], by = bo[c0 + 1];
#pragma unroll
        for (int mi = 0; mi < 4; mi++) {
#pragma unroll
            for (int half = 0; half < 2; half++) {
                const int r = bm + wm*64 + mi*16 + g + half*8;
                float* op = outp + (size_t)r * EMB + c0;
                float2 v = make_float2(acc[mi][ni][half*2 + 0] + bx,
                                       acc[mi][ni][half*2 + 1] + by);
                *(float2*)op = v;
            }
        }
    }
}

// ---------------- flash attention (fp32, passing core) ----------------------
#define ATT_SMEM_FLOATS (64*128 + 64*64 + 64*64 + 64*128)  // 96 KB

__global__ __launch_bounds__(256) void attn_kernel()
{
    extern __shared__ float sm[];
    float* Qs = sm;                  // [64][128]
    float* Ks = Qs + 64*128;         // [64][64]
    float* Vs = Ks + 64*64;          // [64][64]
    float* Ps = Vs + 64*64;          // [64][128]

    const int tid = threadIdx.x;
    const int tx = tid & 15, ty = tid >> 4;
    const int r0 = ty * 8;
    const int c0 = tx * 4;

    const int bh   = blockIdx.y;
    const int qblk = blockIdx.x;
    const float* Qg = g_Q + ((size_t)bh*SEQ + qblk*128)*HD;
    const float* Kg = g_K + (size_t)bh*SEQ*HD;
    const float* Vg = g_V + (size_t)bh*SEQ*HD;

#pragma unroll
    for (int i = 0; i < 8; i++) {
        int s  = tid + i*256;
        int r  = s & 127;
        int d4 = (s >> 7) * 4;
        float4 v = *(const float4*)(Qg + r*HD + d4);
        Qs[(d4+0)*128 + r] = v.x * 8.0f;
        Qs[(d4+1)*128 + r] = v.y * 8.0f;
        Qs[(d4+2)*128 + r] = v.z * 8.0f;
        Qs[(d4+3)*128 + r] = v.w * 8.0f;
    }

    float m_i[8], l_i[8], o[8][4];
#pragma unroll
    for (int i = 0; i < 8; i++) {
        m_i[i] = -1e30f; l_i[i] = 0.f;
#pragma unroll
        for (int j = 0; j < 4; j++) o[i][j] = 0.f;
    }

    for (int kt = 0; kt < SEQ; kt += 64) {
        __syncthreads();
#pragma unroll
        for (int i = 0; i < 4; i++) {
            int s  = tid + i*256;
            int c  = s & 63;
            int d4 = (s >> 6) * 4;
            float4 v = *(const float4*)(Kg + (size_t)(kt + c)*HD + d4);
            Ks[(d4+0)*64 + c] = v.x;
            Ks[(d4+1)*64 + c] = v.y;
            Ks[(d4+2)*64 + c] = v.z;
            Ks[(d4+3)*64 + c] = v.w;
        }
#pragma unroll
        for (int i = 0; i < 4; i++) {
            int s  = tid + i*256;
            int c  = s >> 4;
            int d4 = (s & 15) * 4;
            *(float4*)(Vs + c*HD + d4) = *(const float4*)(Vg + (size_t)(kt + c)*HD + d4);
        }
        __syncthreads();

        float sreg[8][4];
#pragma unroll
        for (int i = 0; i < 8; i++)
#pragma unroll
            for (int j = 0; j < 4; j++) sreg[i][j] = 0.f;

#pragma unroll 8
        for (int d = 0; d < 64; d++) {
            float a[8], bb[4];
            *(float4*)&a[0] = *(const float4*)&Qs[d*128 + r0];
            *(float4*)&a[4] = *(const float4*)&Qs[d*128 + r0 + 4];
            *(float4*)&bb[0] = *(const float4*)&Ks[d*64 + c0];
#pragma unroll
            for (int i = 0; i < 8; i++)
#pragma unroll
                for (int j = 0; j < 4; j++)
                    sreg[i][j] += a[i] * bb[j];
        }

#pragma unroll
        for (int i = 0; i < 8; i++) {
            float mx = fmaxf(fmaxf(sreg[i][0], sreg[i][1]),
                             fmaxf(sreg[i][2], sreg[i][3]));
#pragma unroll
            for (int off = 1; off < 16; off <<= 1)
                mx = fmaxf(mx, __shfl_xor_sync(0xffffffffu, mx, off));
            float nm = fmaxf(m_i[i], mx);
            float al = __expf(m_i[i] - nm);
            m_i[i] = nm;
            float rs = 0.f;
#pragma unroll
            for (int j = 0; j < 4; j++) {
                sreg[i][j] = __expf(sreg[i][j] - nm);
                rs += sreg[i][j];
            }
#pragma unroll
            for (int off = 1; off < 16; off <<= 1)
                rs += __shfl_xor_sync(0xffffffffu, rs, off);
            l_i[i] = l_i[i]*al + rs;
#pragma unroll
            for (int j = 0; j < 4; j++) o[i][j] *= al;
        }

#pragma unroll
        for (int j = 0; j < 4; j++) {
            *(float4*)&Ps[(c0+j)*128 + r0] =
                make_float4(sreg[0][j], sreg[1][j], sreg[2][j], sreg[3][j]);
            *(float4*)&Ps[(c0+j)*128 + r0 + 4] =
                make_float4(sreg[4][j], sreg[5][j], sreg[6][j], sreg[7][j]);
        }
        __syncthreads();

#pragma unroll 8
        for (int c = 0; c < 64; c++) {
            float p[8], vv[4];
            *(float4*)&p[0]  = *(const float4*)&Ps[c*128 + r0];
            *(float4*)&p[4]  = *(const float4*)&Ps[c*128 + r0 + 4];
            *(float4*)&vv[0] = *(const float4*)&Vs[c*HD + c0];
#pragma unroll
            for (int i = 0; i < 8; i++)
#pragma unroll
                for (int j = 0; j < 4; j++)
                    o[i][j] += p[i] * vv[j];
        }
    }

    // Epilogue: normalize and emit Hc directly as bf16 hi/lo split.
    const int b = bh >> 4;
    const int h = bh & 15;
#pragma unroll
    for (int i = 0; i < 8; i++) {
        float inv = 1.0f / l_i[i];
        int tok = qblk*128 + r0 + i;
        size_t base = ((size_t)(b*SEQ + tok))*EMB + h*HD + c0;
        float v0 = o[i][0]*inv, v1 = o[i][1]*inv;
        float v2 = o[i][2]*inv, v3 = o[i][3]*inv;
        __nv_bfloat16 h0 = __float2bfloat16(v0);
        __nv_bfloat16 h1 = __float2bfloat16(v1);
        __nv_bfloat16 h2 = __float2bfloat16(v2);
        __nv_bfloat16 h3 = __float2bfloat16(v3);
        __nv_bfloat16 l0 = __float2bfloat16(v0 - __bfloat162float(h0));
        __nv_bfloat16 l1 = __float2bfloat16(v1 - __bfloat162float(h1));
        __nv_bfloat16 l2 = __float2bfloat16(v2 - __bfloat162float(h2));
        __nv_bfloat16 l3 = __float2bfloat16(v3 - __bfloat162float(h3));
        *(__nv_bfloat162*)(g_Hchi + base)     = __halves2bfloat162(h0, h1);
        *(__nv_bfloat162*)(g_Hchi + base + 2) = __halves2bfloat162(h2, h3);
        *(__nv_bfloat162*)(g_Hclo + base)     = __halves2bfloat162(l0, l1);
        *(__nv_bfloat162*)(g_Hclo + base + 2) = __halves2bfloat162(l2, l3);
    }
}

// ---------------------------------------------------------------------------
extern "C" void kernel_launch(void* const* d_in, const int* in_sizes, int n_in,
                              void* d_out, int out_size)
{
    (void)in_sizes; (void)n_in; (void)out_size;
    const float* x  = (const float*)d_in[0];
    const float* Wq = (const float*)d_in[1];
    const float* bq = (const float*)d_in[2];
    const float* Wk = (const float*)d_in[3];
    const float* bk = (const float*)d_in[4];
    const float* Wv = (const float*)d_in[5];
    const float* bv = (const float*)d_in[6];
    const float* Wo = (const float*)d_in[7];
    const float* bo = (const float*)d_in[8];
    float* out = (float*)d_out;

    cudaFuncSetAttribute(attn_kernel,
                         cudaFuncAttributeMaxDynamicSharedMemorySize,
                         ATT_SMEM_FLOATS * (int)sizeof(float));
    cudaFuncSetAttribute(qkv_gemm_tc,
                         cudaFuncAttributeMaxDynamicSharedMemorySize,
                         GEMM_SMEM_BYTES);
    cudaFuncSetAttribute(out_gemm_tc,
                         cudaFuncAttributeMaxDynamicSharedMemorySize,
                         GEMM_SMEM_BYTES);

    split_kernel<<<dim3(128, 1, 5), 256>>>(x, Wq, Wk, Wv, Wo);
    qkv_gemm_tc<<<dim3(MTOT/128, EMB/128, 3), 256, GEMM_SMEM_BYTES>>>(bq, bk, bv);
    attn_kernel<<<dim3(SEQ/128, BHTOT), 256, ATT_SMEM_FLOATS * sizeof(float)>>>();
    out_gemm_tc<<<dim3(MTOT/128, EMB/128), 256, GEMM_SMEM_BYTES>>>(bo, out);
}

// round 7
// speedup vs baseline: 2.7894x; 2.0038x over previous
#include <cuda_runtime.h>
#include <cuda_bf16.h>
#include <cstdint>

#define SEQ   2048
#define EMB   1024
#define NH    16
#define HD    64
#define BATCH 2
#define MTOT  (BATCH*SEQ)     // 4096
#define BHTOT (BATCH*NH)      // 32

// ---------------- scratch (static device globals; no allocations) ----------
__device__ __nv_bfloat16 g_Xhi[MTOT*EMB],  g_Xlo[MTOT*EMB];
__device__ __nv_bfloat16 g_Wqhi[EMB*EMB],  g_Wqlo[EMB*EMB];
__device__ __nv_bfloat16 g_Wkhi[EMB*EMB],  g_Wklo[EMB*EMB];
__device__ __nv_bfloat16 g_Wvhi[EMB*EMB],  g_Wvlo[EMB*EMB];
__device__ __nv_bfloat16 g_Wohi[EMB*EMB],  g_Wolo[EMB*EMB];
__device__ __nv_bfloat16 g_Hchi[MTOT*EMB], g_Hclo[MTOT*EMB];

// Attention operands (bf16 hi/lo). Q has x8 logit scale folded (exact).
__device__ __nv_bfloat16 g_Qhi[BHTOT*SEQ*HD], g_Qlo[BHTOT*SEQ*HD];
__device__ __nv_bfloat16 g_Khi[BHTOT*SEQ*HD], g_Klo[BHTOT*SEQ*HD];
// V stored transposed: [bh][d][seq]
__device__ __nv_bfloat16 g_Vthi[BHTOT*HD*SEQ], g_Vtlo[BHTOT*HD*SEQ];

// ---------------- PTX helpers (pre-Blackwell features; safe on sm_103) -----
__device__ __forceinline__ uint32_t smem_u32(const void* p) {
    uint32_t a;
    asm("{ .reg .u64 t; cvta.to.shared.u64 t, %1; cvt.u32.u64 %0, t; }"
        : "=r"(a) : "l"(p));
    return a;
}
__device__ __forceinline__ void cp16(uint32_t sdst, const void* gsrc) {
    asm volatile("cp.async.cg.shared.global [%0], [%1], 16;"
                 :: "r"(sdst), "l"(gsrc));
}
__device__ __forceinline__ void ldsm_x4(uint32_t a[4], uint32_t addr) {
    asm volatile("ldmatrix.sync.aligned.m8n8.x4.shared.b16 {%0,%1,%2,%3}, [%4];"
                 : "=r"(a[0]), "=r"(a[1]), "=r"(a[2]), "=r"(a[3]) : "r"(addr));
}
__device__ __forceinline__ void ldsm_x2(uint32_t a[2], uint32_t addr) {
    asm volatile("ldmatrix.sync.aligned.m8n8.x2.shared.b16 {%0,%1}, [%2];"
                 : "=r"(a[0]), "=r"(a[1]) : "r"(addr));
}
__device__ __forceinline__ void mma16816(float d[4], const uint32_t a[4],
                                         const uint32_t b[2]) {
    asm volatile(
        "mma.sync.aligned.m16n8k16.row.col.f32.bf16.bf16.f32 "
        "{%0,%1,%2,%3}, {%4,%5,%6,%7}, {%8,%9}, {%0,%1,%2,%3};"
        : "+f"(d[0]), "+f"(d[1]), "+f"(d[2]), "+f"(d[3])
        : "r"(a[0]), "r"(a[1]), "r"(a[2]), "r"(a[3]), "r"(b[0]), "r"(b[1]));
}
__device__ __forceinline__ uint32_t pack_bf16(float lo, float hi) {
    __nv_bfloat162 t = __halves2bfloat162(__float2bfloat16(lo),
                                          __float2bfloat16(hi));
    return *(uint32_t*)&t;
}

// ---------------- mma.sync GEMM (validated round 6) ------------------------
#define BK 32
#define NCHUNK (EMB/BK)       // 32
#define STRB 80               // smem row stride bytes (32 bf16 + 8 pad)
#define OFF_AHI 0
#define OFF_ALO 10240
#define OFF_BHI 20480
#define OFF_BLO 30720
#define STAGE_BYTES 40960
#define GEMM_SMEM_BYTES (2*STAGE_BYTES)   // 80 KB

__device__ __forceinline__ void gemm_load_chunk(
    uint32_t sb, int stage, int kc, int bm, int bn,
    const __nv_bfloat16* __restrict__ Ahi, const __nv_bfloat16* __restrict__ Alo,
    const __nv_bfloat16* __restrict__ Bhi, const __nv_bfloat16* __restrict__ Blo,
    int tid)
{
    const uint32_t st = sb + stage * STAGE_BYTES;
#pragma unroll
    for (int i = 0; i < 2; i++) {
        int idx = tid + i * 256;
        int row = idx >> 2, ch = idx & 3;
        uint32_t so = (uint32_t)(row * STRB + ch * 16);
        size_t ga = (size_t)(bm + row) * EMB + kc * BK + ch * 8;
        size_t gb = (size_t)(bn + row) * EMB + kc * BK + ch * 8;
        cp16(st + OFF_AHI + so, Ahi + ga);
        cp16(st + OFF_ALO + so, Alo + ga);
        cp16(st + OFF_BHI + so, Bhi + gb);
        cp16(st + OFF_BLO + so, Blo + gb);
    }
    asm volatile("cp.async.commit_group;" ::: "memory");
}

__device__ __forceinline__ void gemm_compute_stage(
    uint32_t sbase, int wm, int wn, int lane, float acc[4][4][4])
{
    const int ra      = lane & 15;
    const uint32_t ka = (uint32_t)((lane >> 4) * 16);
    const int nb      = lane & 7;
    const uint32_t kb = (uint32_t)(((lane >> 3) & 1) * 16);
#pragma unroll
    for (int ks = 0; ks < 2; ks++) {
        uint32_t ah[4][4], al[4][4], bh[4][2], bl[4][2];
#pragma unroll
        for (int mi = 0; mi < 4; mi++) {
            uint32_t r = sbase + (uint32_t)((wm*64 + mi*16 + ra) * STRB) + ks*32 + ka;
            ldsm_x4(ah[mi], r + OFF_AHI);
            ldsm_x4(al[mi], r + OFF_ALO);
        }
#pragma unroll
        for (int ni = 0; ni < 4; ni++) {
            uint32_t r = sbase + (uint32_t)((wn*32 + ni*8 + nb) * STRB) + ks*32 + kb;
            ldsm_x2(bh[ni], r + OFF_BHI);
            ldsm_x2(bl[ni], r + OFF_BLO);
        }
#pragma unroll
        for (int mi = 0; mi < 4; mi++)
#pragma unroll
            for (int ni = 0; ni < 4; ni++) {
                mma16816(acc[mi][ni], ah[mi], bh[ni]);
                mma16816(acc[mi][ni], ah[mi], bl[ni]);
                mma16816(acc[mi][ni], al[mi], bh[ni]);
            }
    }
}

__device__ __forceinline__ void gemm_mainloop(
    uint32_t sb, int bm, int bn,
    const __nv_bfloat16* Ahi, const __nv_bfloat16* Alo,
    const __nv_bfloat16* Bhi, const __nv_bfloat16* Blo,
    int tid, int wm, int wn, int lane, float acc[4][4][4])
{
#pragma unroll
    for (int mi = 0; mi < 4; mi++)
#pragma unroll
        for (int ni = 0; ni < 4; ni++)
#pragma unroll
            for (int q = 0; q < 4; q++) acc[mi][ni][q] = 0.f;

    gemm_load_chunk(sb, 0, 0, bm, bn, Ahi, Alo, Bhi, Blo, tid);

    for (int c = 0; c < NCHUNK; c++) {
        if (c + 1 < NCHUNK) {
            gemm_load_chunk(sb, (c + 1) & 1, c + 1, bm, bn, Ahi, Alo, Bhi, Blo, tid);
            asm volatile("cp.async.wait_group 1;" ::: "memory");
        } else {
            asm volatile("cp.async.wait_group 0;" ::: "memory");
        }
        __syncthreads();
        gemm_compute_stage(sb + (uint32_t)((c & 1) * STAGE_BYTES), wm, wn, lane, acc);
        __syncthreads();
    }
}

// ---------------- split kernel: fp32 -> (bf16 hi, bf16 lo) -----------------
__global__ __launch_bounds__(256) void split_kernel(
    const float* __restrict__ x,
    const float* __restrict__ Wq, const float* __restrict__ Wk,
    const float* __restrict__ Wv, const float* __restrict__ Wo)
{
    const float* src; __nv_bfloat16* hi; __nv_bfloat16* lo; int n4;
    switch (blockIdx.z) {
        case 0:  src = x;  hi = g_Xhi;  lo = g_Xlo;  n4 = MTOT*EMB/4; break;
        case 1:  src = Wq; hi = g_Wqhi; lo = g_Wqlo; n4 = EMB*EMB/4;  break;
        case 2:  src = Wk; hi = g_Wkhi; lo = g_Wklo; n4 = EMB*EMB/4;  break;
        case 3:  src = Wv; hi = g_Wvhi; lo = g_Wvlo; n4 = EMB*EMB/4;  break;
        default: src = Wo; hi = g_Wohi; lo = g_Wolo; n4 = EMB*EMB/4;  break;
    }
    for (int i = blockIdx.x * blockDim.x + threadIdx.x; i < n4;
         i += gridDim.x * blockDim.x) {
        float4 v = ((const float4*)src)[i];
        __nv_bfloat16 h0 = __float2bfloat16(v.x);
        __nv_bfloat16 h1 = __float2bfloat16(v.y);
        __nv_bfloat16 h2 = __float2bfloat16(v.z);
        __nv_bfloat16 h3 = __float2bfloat16(v.w);
        __nv_bfloat16 l0 = __float2bfloat16(v.x - __bfloat162float(h0));
        __nv_bfloat16 l1 = __float2bfloat16(v.y - __bfloat162float(h1));
        __nv_bfloat16 l2 = __float2bfloat16(v.z - __bfloat162float(h2));
        __nv_bfloat16 l3 = __float2bfloat16(v.w - __bfloat162float(h3));
        ((__nv_bfloat162*)hi)[2*i]   = __halves2bfloat162(h0, h1);
        ((__nv_bfloat162*)hi)[2*i+1] = __halves2bfloat162(h2, h3);
        ((__nv_bfloat162*)lo)[2*i]   = __halves2bfloat162(l0, l1);
        ((__nv_bfloat162*)lo)[2*i+1] = __halves2bfloat162(l2, l3);
    }
}

// ---------------- QKV projection: GEMM + bf16 hi/lo epilogue ----------------
__global__ __launch_bounds__(256) void qkv_gemm_tc(
    const float* __restrict__ bq, const float* __restrict__ bk,
    const float* __restrict__ bv)
{
    extern __shared__ char dsm[];
    uint32_t sb = smem_u32(dsm);
    const int tid = threadIdx.x, wid = tid >> 5, lane = tid & 31;
    const int wm = wid >> 2, wn = wid & 3;
    const int bm = blockIdx.x * 128, bn = blockIdx.y * 128;
    const int z = blockIdx.z;

    const __nv_bfloat16 *Bhi, *Blo; const float* bias;
    if (z == 0)      { Bhi = g_Wqhi; Blo = g_Wqlo; bias = bq; }
    else if (z == 1) { Bhi = g_Wkhi; Blo = g_Wklo; bias = bk; }
    else             { Bhi = g_Wvhi; Blo = g_Wvlo; bias = bv; }

    float acc[4][4][4];
    gemm_mainloop(sb, bm, bn, g_Xhi, g_Xlo, Bhi, Blo, tid, wm, wn, lane, acc);

    const int g = lane >> 2, tg = lane & 3;
    const float scl = (z == 0) ? 8.0f : 1.0f;
#pragma unroll
    for (int ni = 0; ni < 4; ni++) {
        const int c0 = bn + wn*32 + ni*8 + 2*tg;
        const float bx = bias[c0], by = bias[c0 + 1];
        const int h  = c0 >> 6;
        const int d0 = c0 & 63;
#pragma unroll
        for (int mi = 0; mi < 4; mi++) {
#pragma unroll
            for (int half = 0; half < 2; half++) {
                const int r = bm + wm*64 + mi*16 + g + half*8;
                const int b = r >> 11;
                const int n = r & (SEQ - 1);
                const int bh = (b << 4) + h;
                float v0 = (acc[mi][ni][half*2 + 0] + bx) * scl;
                float v1 = (acc[mi][ni][half*2 + 1] + by) * scl;
                __nv_bfloat16 h0 = __float2bfloat16(v0);
                __nv_bfloat16 h1 = __float2bfloat16(v1);
                __nv_bfloat16 l0 = __float2bfloat16(v0 - __bfloat162float(h0));
                __nv_bfloat16 l1 = __float2bfloat16(v1 - __bfloat162float(h1));
                if (z == 0) {
                    size_t o = ((size_t)bh * SEQ + n) * HD + d0;
                    *(__nv_bfloat162*)(g_Qhi + o) = __halves2bfloat162(h0, h1);
                    *(__nv_bfloat162*)(g_Qlo + o) = __halves2bfloat162(l0, l1);
                } else if (z == 1) {
                    size_t o = ((size_t)bh * SEQ + n) * HD + d0;
                    *(__nv_bfloat162*)(g_Khi + o) = __halves2bfloat162(h0, h1);
                    *(__nv_bfloat162*)(g_Klo + o) = __halves2bfloat162(l0, l1);
                } else {
                    // V transposed: [bh][d][seq]
                    size_t o0 = ((size_t)bh * HD + d0) * SEQ + n;
                    g_Vthi[o0]       = h0;  g_Vtlo[o0]       = l0;
                    g_Vthi[o0 + SEQ] = h1;  g_Vtlo[o0 + SEQ] = l1;
                }
            }
        }
    }
}

// ---------------- output projection (validated round 6) ---------------------
__global__ __launch_bounds__(256) void out_gemm_tc(
    const float* __restrict__ bo, float* __restrict__ outp)
{
    extern __shared__ char dsm[];
    uint32_t sb = smem_u32(dsm);
    const int tid = threadIdx.x, wid = tid >> 5, lane = tid & 31;
    const int wm = wid >> 2, wn = wid & 3;
    const int bm = blockIdx.x * 128, bn = blockIdx.y * 128;

    float acc[4][4][4];
    gemm_mainloop(sb, bm, bn, g_Hchi, g_Hclo, g_Wohi, g_Wolo,
                  tid, wm, wn, lane, acc);

    const int g = lane >> 2, tg = lane & 3;
#pragma unroll
    for (int ni = 0; ni < 4; ni++) {
        const int c0 = bn + wn*32 + ni*8 + 2*tg;
        const float bx = bo[c0], by = bo[c0 + 1];
#pragma unroll
        for (int mi = 0; mi < 4; mi++) {
#pragma unroll
            for (int half = 0; half < 2; half++) {
                const int r = bm + wm*64 + mi*16 + g + half*8;
                float* op = outp + (size_t)r * EMB + c0;
                float2 v = make_float2(acc[mi][ni][half*2 + 0] + bx,
                                       acc[mi][ni][half*2 + 1] + by);
                *(float2*)op = v;
            }
        }
    }
}

// ---------------- flash attention on HMMA -----------------------------------
// 8 warps x 16 q-rows = 128 q per CTA; K-tile = 64, double-buffered cp.async.
// smem per KV stage: Khi/Klo [64][64+8pad bf16], Vthi/Vtlo [64 d][64+8pad].
#define ASTR 144                      // 64 bf16 + 8 pad = 144 B rows
#define AKHI 0
#define AKLO 9216
#define AVHI 18432
#define AVLO 27648
#define ASTG 36864                    // bytes per stage
#define ATT_SMEM (2*ASTG)             // 72 KB (Q staged in stage 0 first)
#define NKT (SEQ/64)                  // 32

__device__ __forceinline__ void att_load_kv(uint32_t sb, int stage, int kt,
                                            int bh, int tid)
{
    const uint32_t st = sb + stage * ASTG;
    const __nv_bfloat16* kh = g_Khi  + ((size_t)bh*SEQ + kt*64) * HD;
    const __nv_bfloat16* kl = g_Klo  + ((size_t)bh*SEQ + kt*64) * HD;
    const __nv_bfloat16* vh = g_Vthi + (size_t)bh*HD*SEQ + kt*64;
    const __nv_bfloat16* vl = g_Vtlo + (size_t)bh*HD*SEQ + kt*64;
#pragma unroll
    for (int i = 0; i < 2; i++) {
        int idx = tid + i * 256;       // 512 chunks per matrix
        int row = idx >> 3, ch = idx & 7;
        uint32_t so = (uint32_t)(row * ASTR + ch * 16);
        cp16(st + AKHI + so, kh + (size_t)row * HD + ch * 8);
        cp16(st + AKLO + so, kl + (size_t)row * HD + ch * 8);
        cp16(st + AVHI + so, vh + (size_t)row * SEQ + ch * 8);
        cp16(st + AVLO + so, vl + (size_t)row * SEQ + ch * 8);
    }
    asm volatile("cp.async.commit_group;" ::: "memory");
}

__global__ __launch_bounds__(256, 2) void attn_mma()
{
    extern __shared__ char dsm[];
    uint32_t sb = smem_u32(dsm);
    const int tid = threadIdx.x, wid = tid >> 5, lane = tid & 31;
    const int g = lane >> 2, tg = lane & 3;
    const int bh = blockIdx.y, qblk = blockIdx.x;

    // ---- stage Q (hi at sb, lo at sb+18432), then capture A-frags ----
    {
        const __nv_bfloat16* qh = g_Qhi + ((size_t)bh*SEQ + qblk*128) * HD;
        const __nv_bfloat16* ql = g_Qlo + ((size_t)bh*SEQ + qblk*128) * HD;
#pragma unroll
        for (int i = 0; i < 4; i++) {
            int idx = tid + i * 256;   // 1024 chunks per matrix
            int row = idx >> 3, ch = idx & 7;
            uint32_t so = (uint32_t)(row * ASTR + ch * 16);
            cp16(sb + so,         qh + (size_t)row * HD + ch * 8);
            cp16(sb + 18432 + so, ql + (size_t)row * HD + ch * 8);
        }
        asm volatile("cp.async.commit_group;" ::: "memory");
        asm volatile("cp.async.wait_group 0;" ::: "memory");
        __syncthreads();
    }
    uint32_t qh[4][4], ql[4][4];
    {
        uint32_t qa = sb + (uint32_t)((wid*16 + (lane & 15)) * ASTR)
                         + (uint32_t)((lane >> 4) * 16);
#pragma unroll
        for (int ks = 0; ks < 4; ks++) {
            ldsm_x4(qh[ks], qa + ks*32);
            ldsm_x4(ql[ks], qa + 18432 + ks*32);
        }
    }
    __syncthreads();   // Q smem region free for KV stage 0

    float oacc[8][4];
#pragma unroll
    for (int nf = 0; nf < 8; nf++)
#pragma unroll
        for (int q = 0; q < 4; q++) oacc[nf][q] = 0.f;
    float m_a = -1e30f, m_b = -1e30f, l_a = 0.f, l_b = 0.f;

    const int nb = lane & 7;
    const uint32_t kb = (uint32_t)(((lane >> 3) & 1) * 16);

    att_load_kv(sb, 0, 0, bh, tid);

    for (int t = 0; t < NKT; t++) {
        if (t + 1 < NKT) {
            att_load_kv(sb, (t + 1) & 1, t + 1, bh, tid);
            asm volatile("cp.async.wait_group 1;" ::: "memory");
        } else {
            asm volatile("cp.async.wait_group 0;" ::: "memory");
        }
        __syncthreads();
        const uint32_t st = sb + (uint32_t)((t & 1) * ASTG);

        // ---- S = Q K^T (3-pass hi/lo, fp32 accum) ----
        float sacc[8][4];
#pragma unroll
        for (int nf = 0; nf < 8; nf++)
#pragma unroll
            for (int q = 0; q < 4; q++) sacc[nf][q] = 0.f;

#pragma unroll
        for (int ks = 0; ks < 4; ks++) {
#pragma unroll
            for (int nf = 0; nf < 8; nf++) {
                uint32_t ka = st + (uint32_t)((nf*8 + nb) * ASTR) + kb + ks*32;
                uint32_t bhh[2], bll[2];
                ldsm_x2(bhh, ka + AKHI);
                ldsm_x2(bll, ka + AKLO);
                mma16816(sacc[nf], qh[ks], bhh);
                mma16816(sacc[nf], ql[ks], bhh);
                mma16816(sacc[nf], qh[ks], bll);
            }
        }

        // ---- online softmax (rows g and g+8; reduce over tg lanes) ----
        float mx_a = sacc[0][0], mx_b = sacc[0][2];
#pragma unroll
        for (int nf = 0; nf < 8; nf++) {
            mx_a = fmaxf(mx_a, fmaxf(sacc[nf][0], sacc[nf][1]));
            mx_b = fmaxf(mx_b, fmaxf(sacc[nf][2], sacc[nf][3]));
        }
        mx_a = fmaxf(mx_a, __shfl_xor_sync(0xffffffffu, mx_a, 1));
        mx_a = fmaxf(mx_a, __shfl_xor_sync(0xffffffffu, mx_a, 2));
        mx_b = fmaxf(mx_b, __shfl_xor_sync(0xffffffffu, mx_b, 1));
        mx_b = fmaxf(mx_b, __shfl_xor_sync(0xffffffffu, mx_b, 2));

        float mna = fmaxf(m_a, mx_a), mnb = fmaxf(m_b, mx_b);
        float ala = __expf(m_a - mna), alb = __expf(m_b - mnb);
        m_a = mna; m_b = mnb;

        // exp + bf16 hi/lo split into P A-fragments (C layout == A layout)
        uint32_t phi[4][4], plo[4][4];
        float rs_a = 0.f, rs_b = 0.f;
#pragma unroll
        for (int ks = 0; ks < 4; ks++) {
#pragma unroll
            for (int jj = 0; jj < 2; jj++) {
                const int nf = 2*ks + jj;
                float p0 = __expf(sacc[nf][0] - m_a);
                float p1 = __expf(sacc[nf][1] - m_a);
                float p2 = __expf(sacc[nf][2] - m_b);
                float p3 = __expf(sacc[nf][3] - m_b);
                rs_a += p0 + p1; rs_b += p2 + p3;
                float h0f = __bfloat162float(__float2bfloat16(p0));
                float h1f = __bfloat162float(__float2bfloat16(p1));
                float h2f = __bfloat162float(__float2bfloat16(p2));
                float h3f = __bfloat162float(__float2bfloat16(p3));
                phi[ks][2*jj + 0] = pack_bf16(h0f, h1f);
                phi[ks][2*jj + 1] = pack_bf16(h2f, h3f);
                plo[ks][2*jj + 0] = pack_bf16(p0 - h0f, p1 - h1f);
                plo[ks][2*jj + 1] = pack_bf16(p2 - h2f, p3 - h3f);
            }
        }
        rs_a += __shfl_xor_sync(0xffffffffu, rs_a, 1);
        rs_a += __shfl_xor_sync(0xffffffffu, rs_a, 2);
        rs_b += __shfl_xor_sync(0xffffffffu, rs_b, 1);
        rs_b += __shfl_xor_sync(0xffffffffu, rs_b, 2);
        l_a = l_a * ala + rs_a;
        l_b = l_b * alb + rs_b;
#pragma unroll
        for (int nf = 0; nf < 8; nf++) {
            oacc[nf][0] *= ala; oacc[nf][1] *= ala;
            oacc[nf][2] *= alb; oacc[nf][3] *= alb;
        }

        // ---- O += P V (3-pass hi/lo) ----
#pragma unroll
        for (int ks = 0; ks < 4; ks++) {
#pragma unroll
            for (int nf = 0; nf < 8; nf++) {
                uint32_t va = st + (uint32_t)((nf*8 + nb) * ASTR) + kb + ks*32;
                uint32_t vhh[2], vll[2];
                ldsm_x2(vhh, va + AVHI);
                ldsm_x2(vll, va + AVLO);
                mma16816(oacc[nf], phi[ks], vhh);
                mma16816(oacc[nf], plo[ks], vhh);
                mma16816(oacc[nf], phi[ks], vll);
            }
        }
        __syncthreads();
    }

    // ---- epilogue: normalize, emit Hc hi/lo bf16 ----
    const float iva = 1.0f / l_a, ivb = 1.0f / l_b;
    const int b = bh >> 4, h = bh & 15;
    const int tok_a = qblk*128 + wid*16 + g;
    const int tok_b = tok_a + 8;
#pragma unroll
    for (int nf = 0; nf < 8; nf++) {
        const int d = h*HD + nf*8 + 2*tg;
        float v0 = oacc[nf][0]*iva, v1 = oacc[nf][1]*iva;
        float v2 = oacc[nf][2]*ivb, v3 = oacc[nf][3]*ivb;
        size_t oa = ((size_t)(b*SEQ + tok_a))*EMB + d;
        size_t ob = ((size_t)(b*SEQ + tok_b))*EMB + d;
        __nv_bfloat16 h0 = __float2bfloat16(v0);
        __nv_bfloat16 h1 = __float2bfloat16(v1);
        __nv_bfloat16 h2 = __float2bfloat16(v2);
        __nv_bfloat16 h3 = __float2bfloat16(v3);
        *(__nv_bfloat162*)(g_Hchi + oa) = __halves2bfloat162(h0, h1);
        *(__nv_bfloat162*)(g_Hchi + ob) = __halves2bfloat162(h2, h3);
        *(__nv_bfloat162*)(g_Hclo + oa) = __halves2bfloat162(
            __float2bfloat16(v0 - __bfloat162float(h0)),
            __float2bfloat16(v1 - __bfloat162float(h1)));
        *(__nv_bfloat162*)(g_Hclo + ob) = __halves2bfloat162(
            __float2bfloat16(v2 - __bfloat162float(h2)),
            __float2bfloat16(v3 - __bfloat162float(h3)));
    }
}

// ---------------------------------------------------------------------------
extern "C" void kernel_launch(void* const* d_in, const int* in_sizes, int n_in,
                              void* d_out, int out_size)
{
    (void)in_sizes; (void)n_in; (void)out_size;
    const float* x  = (const float*)d_in[0];
    const float* Wq = (const float*)d_in[1];
    const float* bq = (const float*)d_in[2];
    const float* Wk = (const float*)d_in[3];
    const float* bk = (const float*)d_in[4];
    const float* Wv = (const float*)d_in[5];
    const float* bv = (const float*)d_in[6];
    const float* Wo = (const float*)d_in[7];
    const float* bo = (const float*)d_in[8];
    float* out = (float*)d_out;

    cudaFuncSetAttribute(qkv_gemm_tc,
                         cudaFuncAttributeMaxDynamicSharedMemorySize,
                         GEMM_SMEM_BYTES);
    cudaFuncSetAttribute(out_gemm_tc,
                         cudaFuncAttributeMaxDynamicSharedMemorySize,
                         GEMM_SMEM_BYTES);
    cudaFuncSetAttribute(attn_mma,
                         cudaFuncAttributeMaxDynamicSharedMemorySize,
                         ATT_SMEM);

    split_kernel<<<dim3(128, 1, 5), 256>>>(x, Wq, Wk, Wv, Wo);
    qkv_gemm_tc<<<dim3(MTOT/128, EMB/128, 3), 256, GEMM_SMEM_BYTES>>>(bq, bk, bv);
    attn_mma<<<dim3(SEQ/128, BHTOT), 256, ATT_SMEM>>>();
    out_gemm_tc<<<dim3(MTOT/128, EMB/128), 256, GEMM_SMEM_BYTES>>>(bo, out);
}